// round 11
// baseline (speedup 1.0000x reference)
#include <cuda_runtime.h>
#include <cuda_fp16.h>
#include <cstdint>

#define C 128
#define N_MAX 16384
#define E_MAX 1100000
#define CAP 256
#define WPN 4               // warps per node
#define NPB 2               // nodes per 256-thread block

// Static scratch (no allocs allowed)
__device__ int g_idx64;
__device__ int g_cnt[N_MAX];
__device__ int g_ssrc[N_MAX * CAP];           // bucketed src ids (always valid node ids)
__device__ int g_ovf_cnt;
__device__ long long g_ovf[E_MAX];            // overflow edges (dst<<32 | src)
__device__ __half g_xh[N_MAX * C];            // fp16 copy of x for gather stream

__global__ void detect_idx_kernel(const void* __restrict__ ei, int n_nodes) {
    if (threadIdx.x == 0 && blockIdx.x == 0) {
        const long long* p = (const long long*)ei;
        int ok = 1;
        #pragma unroll
        for (int i = 0; i < 16; i++) {
            long long v = p[i];
            if (v < 0 || v >= (long long)n_nodes) { ok = 0; }
        }
        g_idx64 = ok;
    }
}

// Merged prep: fp32->fp16 convert of x, then bucket edges by destination.
__global__ void prep_kernel(const float* __restrict__ x,
                            const void* __restrict__ ei,
                            int n_edges, int n_nodes, int n_f4) {
    __shared__ int s_idx64;
    if (threadIdx.x == 0) {
        const long long* p = (const long long*)ei;
        int ok = 1;
        #pragma unroll
        for (int i = 0; i < 16; i++) {
            long long v = p[i];
            if (v < 0 || v >= (long long)n_nodes) { ok = 0; }
        }
        s_idx64 = ok;
    }

    int gid = blockIdx.x * blockDim.x + threadIdx.x;
    int stride = gridDim.x * blockDim.x;

    for (int i = gid; i < n_f4; i += stride) {
        float4 v = __ldg((const float4*)x + i);
        __half2 h0 = __floats2half2_rn(v.x, v.y);
        __half2 h1 = __floats2half2_rn(v.z, v.w);
        uint2 u;
        u.x = *reinterpret_cast<unsigned*>(&h0);
        u.y = *reinterpret_cast<unsigned*>(&h1);
        ((uint2*)g_xh)[i] = u;
    }

    __syncthreads();
    const int idx64 = s_idx64;

    const long long* p64 = (const long long*)ei;
    const int*       p32 = (const int*)ei;
    for (int e = gid; e < n_edges; e += stride) {
        int s, d;
        if (idx64) {
            s = (int)__ldg(p64 + e);
            d = (int)__ldg(p64 + n_edges + e);
        } else {
            s = __ldg(p32 + e);
            d = __ldg(p32 + n_edges + e);
        }
        int pos = atomicAdd(&g_cnt[d], 1);
        if (pos < CAP) {
            g_ssrc[d * CAP + pos] = s;
        } else {
            int o = atomicAdd(&g_ovf_cnt, 1);
            g_ovf[o] = ((long long)d << 32) | (unsigned)s;
        }
    }
}

// 4 warps per node, 2 nodes per block. Lane owns channels [4*lane, 4*lane+4)
// (one uint2 fp16 load per row). Each warp takes edges sub*4 + k*16 .. +3;
// partials combined in smem, sub==0 applies W2 and stores.
__global__ __launch_bounds__(256) void gather_kernel(
    const float* __restrict__ x,
    const float* __restrict__ W2,
    const float* __restrict__ W3,
    float* __restrict__ out,
    int n_nodes)
{
    __shared__ float4 s_acc[8][32];

    const int lane = threadIdx.x & 31;
    const int warp = threadIdx.x >> 5;
    const int sub = warp & (WPN - 1);
    const int j = blockIdx.x * NPB + (warp >> 2);
    const bool active = (j < n_nodes);

    float4 w3xj = make_float4(0.f, 0.f, 0.f, 0.f);
    int deg_raw = 0;
    if (active) {
        float4 xj = __ldg((const float4*)(x + (long long)j * C) + lane);
        float4 w3 = __ldg((const float4*)W3 + lane);
        w3xj.x = w3.x * xj.x; w3xj.y = w3.y * xj.y;
        w3xj.z = w3.z * xj.z; w3xj.w = w3.w * xj.w;
        deg_raw = __ldg(&g_cnt[j]);
    }
    const int deg = (deg_raw > CAP) ? CAP : deg_raw;
    const int* bucket = &g_ssrc[j * CAP];

    float4 acc = make_float4(0.f, 0.f, 0.f, 0.f);

    for (int i = sub * 4; i < deg; i += WPN * 4) {
        int4 sv = __ldg((const int4*)(bucket + i));   // 16B-aligned; over-read slots hold valid ids

        uint2 u0 = __ldg((const uint2*)(g_xh + (long long)sv.x * C) + lane);
        uint2 u1 = __ldg((const uint2*)(g_xh + (long long)sv.y * C) + lane);
        uint2 u2 = __ldg((const uint2*)(g_xh + (long long)sv.z * C) + lane);
        uint2 u3 = __ldg((const uint2*)(g_xh + (long long)sv.w * C) + lane);

        float2 a0 = __half22float2(*(__half2*)&u0.x), b0 = __half22float2(*(__half2*)&u0.y);
        float2 a1 = __half22float2(*(__half2*)&u1.x), b1 = __half22float2(*(__half2*)&u1.y);
        float2 a2 = __half22float2(*(__half2*)&u2.x), b2 = __half22float2(*(__half2*)&u2.y);
        float2 a3 = __half22float2(*(__half2*)&u3.x), b3 = __half22float2(*(__half2*)&u3.y);

        float p0 = a0.x * w3xj.x + a0.y * w3xj.y + b0.x * w3xj.z + b0.y * w3xj.w;
        float p1 = a1.x * w3xj.x + a1.y * w3xj.y + b1.x * w3xj.z + b1.y * w3xj.w;
        float p2 = a2.x * w3xj.x + a2.y * w3xj.y + b2.x * w3xj.z + b2.y * w3xj.w;
        float p3 = a3.x * w3xj.x + a3.y * w3xj.y + b3.x * w3xj.z + b3.y * w3xj.w;
        #pragma unroll
        for (int o = 16; o > 0; o >>= 1) {
            p0 += __shfl_xor_sync(0xffffffffu, p0, o);
            p1 += __shfl_xor_sync(0xffffffffu, p1, o);
            p2 += __shfl_xor_sync(0xffffffffu, p2, o);
            p3 += __shfl_xor_sync(0xffffffffu, p3, o);
        }
        if (i + 1 >= deg) p1 = 0.f;
        if (i + 2 >= deg) p2 = 0.f;
        if (i + 3 >= deg) p3 = 0.f;

        acc.x += p0 * a0.x + p1 * a1.x + p2 * a2.x + p3 * a3.x;
        acc.y += p0 * a0.y + p1 * a1.y + p2 * a2.y + p3 * a3.y;
        acc.z += p0 * b0.x + p1 * b1.x + p2 * b2.x + p3 * b3.x;
        acc.w += p0 * b0.y + p1 * b1.y + p2 * b2.y + p3 * b3.y;
    }

    // Rare: node overflowed CAP — sub==0 warp scans the overflow list.
    if (deg_raw > CAP && sub == 0) {
        int n = g_ovf_cnt;
        for (int e2 = 0; e2 < n; e2++) {
            long long pk = g_ovf[e2];
            if ((int)(pk >> 32) != j) continue;
            int s = (int)(unsigned)(pk & 0xffffffffLL);
            uint2 u0 = __ldg((const uint2*)(g_xh + (long long)s * C) + lane);
            float2 a0 = __half22float2(*(__half2*)&u0.x), b0 = __half22float2(*(__half2*)&u0.y);
            float p0 = a0.x * w3xj.x + a0.y * w3xj.y + b0.x * w3xj.z + b0.y * w3xj.w;
            #pragma unroll
            for (int o = 16; o > 0; o >>= 1)
                p0 += __shfl_xor_sync(0xffffffffu, p0, o);
            acc.x += p0 * a0.x; acc.y += p0 * a0.y;
            acc.z += p0 * b0.x; acc.w += p0 * b0.y;
        }
    }

    s_acc[warp][lane] = acc;
    __syncthreads();

    if (sub == 0 && active) {
        #pragma unroll
        for (int k = 1; k < WPN; k++) {
            float4 o = s_acc[warp + k][lane];
            acc.x += o.x; acc.y += o.y; acc.z += o.z; acc.w += o.w;
        }
        float4 w2 = __ldg((const float4*)W2 + lane);
        float4 r;
        r.x = acc.x * w2.x; r.y = acc.y * w2.y;
        r.z = acc.z * w2.z; r.w = acc.w * w2.w;
        ((float4*)(out + (long long)j * C))[lane] = r;
    }
}

// ---------------- Fallback (R5 kernel) for unexpected shapes ----------------
__global__ __launch_bounds__(256, 4) void edge_scatter_kernel(
    const float* __restrict__ x, const void* __restrict__ ei,
    const float* __restrict__ W2, const float* __restrict__ W3,
    float* __restrict__ out, int n_edges)
{
    const int lane = threadIdx.x & 31;
    const int t = lane & 7;
    const int grp = lane >> 3;
    const int warp_id = (int)((blockIdx.x * (unsigned)blockDim.x + threadIdx.x) >> 5);
    const int n_warps = (int)((gridDim.x * (unsigned)blockDim.x) >> 5);

    float4 w2v[4], w3v[4];
    #pragma unroll
    for (int k = 0; k < 4; k++) {
        w3v[k] = __ldg((const float4*)W3 + (t + 8 * k));
        w2v[k] = __ldg((const float4*)W2 + (t + 8 * k));
    }
    const int idx64 = g_idx64;
    const long long* p64 = (const long long*)ei;
    const int*       p32 = (const int*)ei;

    for (int base = warp_id * 4; base < n_edges; base += n_warps * 4) {
        int e = base + grp;
        bool valid = (e < n_edges);
        int ec = valid ? e : (n_edges - 1);
        long long src, dst;
        if (idx64) { src = __ldg(p64 + ec); dst = __ldg(p64 + n_edges + ec); }
        else { src = (long long)__ldg(p32 + ec); dst = (long long)__ldg(p32 + n_edges + ec); }

        const float4* srow = (const float4*)(x + src * C);
        const float4* drow = (const float4*)(x + dst * C);
        float4 vs[4], vd[4];
        #pragma unroll
        for (int k = 0; k < 4; k++) vs[k] = __ldg(srow + (t + 8 * k));
        #pragma unroll
        for (int k = 0; k < 4; k++) vd[k] = __ldg(drow + (t + 8 * k));

        float part = 0.f;
        #pragma unroll
        for (int k = 0; k < 4; k++)
            part += vs[k].x * w3v[k].x * vd[k].x + vs[k].y * w3v[k].y * vd[k].y
                  + vs[k].z * w3v[k].z * vd[k].z + vs[k].w * w3v[k].w * vd[k].w;
        part += __shfl_xor_sync(0xffffffffu, part, 4);
        part += __shfl_xor_sync(0xffffffffu, part, 2);
        part += __shfl_xor_sync(0xffffffffu, part, 1);

        if (valid) {
            float* op = out + dst * C;
            #pragma unroll
            for (int k = 0; k < 4; k++) {
                float4 r;
                r.x = part * vs[k].x * w2v[k].x; r.y = part * vs[k].y * w2v[k].y;
                r.z = part * vs[k].z * w2v[k].z; r.w = part * vs[k].w * w2v[k].w;
                asm volatile("red.global.add.v4.f32 [%0], {%1,%2,%3,%4};"
                             :: "l"(op + (t + 8 * k) * 4),
                                "f"(r.x), "f"(r.y), "f"(r.z), "f"(r.w) : "memory");
            }
        }
    }
}

extern "C" void kernel_launch(void* const* d_in, const int* in_sizes, int n_in,
                              void* d_out, int out_size) {
    const float* x  = (const float*)d_in[0];
    const void*  ei = d_in[1];
    const float* W2 = (const float*)d_in[2];
    const float* W3 = (const float*)d_in[3];
    float* out = (float*)d_out;

    int n_nodes = in_sizes[0] / C;
    int n_edges = in_sizes[1] / 2;

    if (n_nodes <= N_MAX && n_edges <= E_MAX) {
        void* cnt_ptr = nullptr;
        void* ovf_ptr = nullptr;
        cudaGetSymbolAddress(&cnt_ptr, g_cnt);
        cudaGetSymbolAddress(&ovf_ptr, g_ovf_cnt);
        cudaMemsetAsync(cnt_ptr, 0, (size_t)n_nodes * sizeof(int), 0);
        cudaMemsetAsync(ovf_ptr, 0, sizeof(int), 0);

        int n_f4 = n_nodes * (C / 4);
        prep_kernel<<<512, 256>>>(x, ei, n_edges, n_nodes, n_f4);

        int blocks = (n_nodes + NPB - 1) / NPB;
        gather_kernel<<<blocks, 256>>>(x, W2, W3, out, n_nodes);
    } else {
        detect_idx_kernel<<<1, 32>>>(ei, n_nodes);
        cudaMemsetAsync(out, 0, (size_t)out_size * sizeof(float), 0);
        edge_scatter_kernel<<<2048, 256>>>(x, ei, W2, W3, out, n_edges);
    }
}

// round 12
// speedup vs baseline: 1.2508x; 1.2508x over previous
#include <cuda_runtime.h>
#include <cuda_fp16.h>
#include <cstdint>

#define C 128
#define N_MAX 16384
#define E_MAX 1100000
#define CAP 256

// Static scratch (no allocs allowed)
__device__ int g_idx64;
__device__ int g_cnt[N_MAX];
__device__ int g_ssrc[N_MAX * CAP];           // bucketed src ids
__device__ int g_ovf_cnt;
__device__ long long g_ovf[E_MAX];            // overflow edges (dst<<32 | src)
__device__ __half g_xh[N_MAX * C];            // fp16 copy of x for gather stream

__global__ void detect_idx_kernel(const void* __restrict__ ei, int n_nodes) {
    if (threadIdx.x == 0 && blockIdx.x == 0) {
        const long long* p = (const long long*)ei;
        int ok = 1;
        #pragma unroll
        for (int i = 0; i < 16; i++) {
            long long v = p[i];
            if (v < 0 || v >= (long long)n_nodes) { ok = 0; }
        }
        g_idx64 = ok;
    }
}

// Merged prep: fp32->fp16 convert of x, then bucket edges by destination.
__global__ void prep_kernel(const float* __restrict__ x,
                            const void* __restrict__ ei,
                            int n_edges, int n_nodes, int n_f4) {
    __shared__ int s_idx64;
    if (threadIdx.x == 0) {
        const long long* p = (const long long*)ei;
        int ok = 1;
        #pragma unroll
        for (int i = 0; i < 16; i++) {
            long long v = p[i];
            if (v < 0 || v >= (long long)n_nodes) { ok = 0; }
        }
        s_idx64 = ok;
    }

    int gid = blockIdx.x * blockDim.x + threadIdx.x;
    int stride = gridDim.x * blockDim.x;

    for (int i = gid; i < n_f4; i += stride) {
        float4 v = __ldg((const float4*)x + i);
        __half2 h0 = __floats2half2_rn(v.x, v.y);
        __half2 h1 = __floats2half2_rn(v.z, v.w);
        uint2 u;
        u.x = *reinterpret_cast<unsigned*>(&h0);
        u.y = *reinterpret_cast<unsigned*>(&h1);
        ((uint2*)g_xh)[i] = u;
    }

    __syncthreads();
    const int idx64 = s_idx64;

    const long long* p64 = (const long long*)ei;
    const int*       p32 = (const int*)ei;
    for (int e = gid; e < n_edges; e += stride) {
        int s, d;
        if (idx64) {
            s = (int)__ldg(p64 + e);
            d = (int)__ldg(p64 + n_edges + e);
        } else {
            s = __ldg(p32 + e);
            d = __ldg(p32 + n_edges + e);
        }
        int pos = atomicAdd(&g_cnt[d], 1);
        if (pos < CAP) {
            g_ssrc[d * CAP + pos] = s;
        } else {
            int o = atomicAdd(&g_ovf_cnt, 1);
            g_ovf[o] = ((long long)d << 32) | (unsigned)s;
        }
    }
}

// Transposed 4-value warp reduction. Input: per-lane partials p0..p3 for 4
// independent edges. Output: full sums A0..A3 broadcast to all lanes.
// 10 SHFL total (vs 20 for four plain butterflies).
__device__ __forceinline__ void reduce4(float p0, float p1, float p2, float p3,
                                        float& A0, float& A1, float& A2, float& A3,
                                        int lane)
{
    const unsigned FULL = 0xffffffffu;
    bool lo16 = (lane & 16) == 0;
    // level 16: q01 lower-half accumulates e0, upper-half e1 (same for q23/e2,e3)
    float q01 = (lo16 ? p0 : p1) + __shfl_xor_sync(FULL, lo16 ? p1 : p0, 16);
    float q23 = (lo16 ? p2 : p3) + __shfl_xor_sync(FULL, lo16 ? p3 : p2, 16);
    // level 8: lanes 0-7 -> e0, 8-15 -> e2, 16-23 -> e1, 24-31 -> e3
    bool lo8 = (lane & 8) == 0;
    float r = (lo8 ? q01 : q23) + __shfl_xor_sync(FULL, lo8 ? q23 : q01, 8);
    // levels 4,2,1 within each 8-lane group
    r += __shfl_xor_sync(FULL, r, 4);
    r += __shfl_xor_sync(FULL, r, 2);
    r += __shfl_xor_sync(FULL, r, 1);
    A0 = __shfl_sync(FULL, r, 0);
    A2 = __shfl_sync(FULL, r, 8);
    A1 = __shfl_sync(FULL, r, 16);
    A3 = __shfl_sync(FULL, r, 24);
}

// One warp per destination node (R8 geometry). Lane owns channels
// [4*lane, 4*lane+4). Software pipeline: indices prefetched 2 iters ahead,
// rows 1 iter ahead, so the steady-state loop never waits on its own loads.
__global__ __launch_bounds__(256) void gather_kernel(
    const float* __restrict__ x,
    const float* __restrict__ W2,
    const float* __restrict__ W3,
    float* __restrict__ out,
    int n_nodes)
{
    const int lane = threadIdx.x & 31;
    const int j = (int)((blockIdx.x * (unsigned)blockDim.x + threadIdx.x) >> 5);
    if (j >= n_nodes) return;

    float4 xj = __ldg((const float4*)(x + (long long)j * C) + lane);
    float4 w3 = __ldg((const float4*)W3 + lane);
    float4 w3xj;
    w3xj.x = w3.x * xj.x; w3xj.y = w3.y * xj.y;
    w3xj.z = w3.z * xj.z; w3xj.w = w3.w * xj.w;

    float4 acc = make_float4(0.f, 0.f, 0.f, 0.f);

    const int deg_raw = __ldg(&g_cnt[j]);
    const int deg = (deg_raw > CAP) ? CAP : deg_raw;
    const int* bucket = &g_ssrc[j * CAP];

    if (deg > 0) {
        // Prologue: indices for iter 0 and iter 1; rows for iter 0.
        int4 sv_nxt = __ldg((const int4*)bucket);          // iter 0 indices
        uint2 uc0, uc1, uc2, uc3;
        {
            uc0 = __ldg((const uint2*)(g_xh + (long long)sv_nxt.x * C) + lane);
            uc1 = __ldg((const uint2*)(g_xh + (long long)sv_nxt.y * C) + lane);
            uc2 = __ldg((const uint2*)(g_xh + (long long)sv_nxt.z * C) + lane);
            uc3 = __ldg((const uint2*)(g_xh + (long long)sv_nxt.w * C) + lane);
        }
        sv_nxt = __ldg((const int4*)(bucket + ((4 < deg) ? 4 : 0)));  // iter 1 indices

        for (int i = 0; i < deg; i += 4) {
            // Prefetch indices for iter i+8 (consumed 2 iterations from now).
            int pf = (i + 8 < deg) ? (i + 8) : 0;
            int4 sv_fut = __ldg((const int4*)(bucket + pf));

            // Prefetch rows for the NEXT iteration (sv_nxt loaded last iter).
            uint2 un0 = __ldg((const uint2*)(g_xh + (long long)sv_nxt.x * C) + lane);
            uint2 un1 = __ldg((const uint2*)(g_xh + (long long)sv_nxt.y * C) + lane);
            uint2 un2 = __ldg((const uint2*)(g_xh + (long long)sv_nxt.z * C) + lane);
            uint2 un3 = __ldg((const uint2*)(g_xh + (long long)sv_nxt.w * C) + lane);

            // Compute on current rows (loaded one iteration ago).
            float2 a0 = __half22float2(*(__half2*)&uc0.x), b0 = __half22float2(*(__half2*)&uc0.y);
            float2 a1 = __half22float2(*(__half2*)&uc1.x), b1 = __half22float2(*(__half2*)&uc1.y);
            float2 a2 = __half22float2(*(__half2*)&uc2.x), b2 = __half22float2(*(__half2*)&uc2.y);
            float2 a3 = __half22float2(*(__half2*)&uc3.x), b3 = __half22float2(*(__half2*)&uc3.y);

            float p0 = a0.x * w3xj.x + a0.y * w3xj.y + b0.x * w3xj.z + b0.y * w3xj.w;
            float p1 = a1.x * w3xj.x + a1.y * w3xj.y + b1.x * w3xj.z + b1.y * w3xj.w;
            float p2 = a2.x * w3xj.x + a2.y * w3xj.y + b2.x * w3xj.z + b2.y * w3xj.w;
            float p3 = a3.x * w3xj.x + a3.y * w3xj.y + b3.x * w3xj.z + b3.y * w3xj.w;

            float A0, A1, A2, A3;
            reduce4(p0, p1, p2, p3, A0, A1, A2, A3, lane);

            // Tail masking: invalid edges contribute zero.
            if (i + 1 >= deg) A1 = 0.f;
            if (i + 2 >= deg) A2 = 0.f;
            if (i + 3 >= deg) A3 = 0.f;

            acc.x += A0 * a0.x + A1 * a1.x + A2 * a2.x + A3 * a3.x;
            acc.y += A0 * a0.y + A1 * a1.y + A2 * a2.y + A3 * a3.y;
            acc.z += A0 * b0.x + A1 * b1.x + A2 * b2.x + A3 * b3.x;
            acc.w += A0 * b0.y + A1 * b1.y + A2 * b2.y + A3 * b3.y;

            // Rotate pipeline.
            uc0 = un0; uc1 = un1; uc2 = un2; uc3 = un3;
            sv_nxt = sv_fut;
        }
    }

    // Rare: node overflowed CAP — its warp scans the overflow list.
    if (deg_raw > CAP) {
        int n = g_ovf_cnt;
        for (int e2 = 0; e2 < n; e2++) {
            long long pk = g_ovf[e2];
            if ((int)(pk >> 32) != j) continue;
            int s = (int)(unsigned)(pk & 0xffffffffLL);
            uint2 u0 = __ldg((const uint2*)(g_xh + (long long)s * C) + lane);
            float2 a0 = __half22float2(*(__half2*)&u0.x), b0 = __half22float2(*(__half2*)&u0.y);
            float p0 = a0.x * w3xj.x + a0.y * w3xj.y + b0.x * w3xj.z + b0.y * w3xj.w;
            #pragma unroll
            for (int o = 16; o > 0; o >>= 1)
                p0 += __shfl_xor_sync(0xffffffffu, p0, o);
            acc.x += p0 * a0.x; acc.y += p0 * a0.y;
            acc.z += p0 * b0.x; acc.w += p0 * b0.y;
        }
    }

    float4 w2 = __ldg((const float4*)W2 + lane);
    float4 r;
    r.x = acc.x * w2.x; r.y = acc.y * w2.y;
    r.z = acc.z * w2.z; r.w = acc.w * w2.w;
    ((float4*)(out + (long long)j * C))[lane] = r;
}

// ---------------- Fallback (R5 kernel) for unexpected shapes ----------------
__global__ __launch_bounds__(256, 4) void edge_scatter_kernel(
    const float* __restrict__ x, const void* __restrict__ ei,
    const float* __restrict__ W2, const float* __restrict__ W3,
    float* __restrict__ out, int n_edges)
{
    const int lane = threadIdx.x & 31;
    const int t = lane & 7;
    const int grp = lane >> 3;
    const int warp_id = (int)((blockIdx.x * (unsigned)blockDim.x + threadIdx.x) >> 5);
    const int n_warps = (int)((gridDim.x * (unsigned)blockDim.x) >> 5);

    float4 w2v[4], w3v[4];
    #pragma unroll
    for (int k = 0; k < 4; k++) {
        w3v[k] = __ldg((const float4*)W3 + (t + 8 * k));
        w2v[k] = __ldg((const float4*)W2 + (t + 8 * k));
    }
    const int idx64 = g_idx64;
    const long long* p64 = (const long long*)ei;
    const int*       p32 = (const int*)ei;

    for (int base = warp_id * 4; base < n_edges; base += n_warps * 4) {
        int e = base + grp;
        bool valid = (e < n_edges);
        int ec = valid ? e : (n_edges - 1);
        long long src, dst;
        if (idx64) { src = __ldg(p64 + ec); dst = __ldg(p64 + n_edges + ec); }
        else { src = (long long)__ldg(p32 + ec); dst = (long long)__ldg(p32 + n_edges + ec); }

        const float4* srow = (const float4*)(x + src * C);
        const float4* drow = (const float4*)(x + dst * C);
        float4 vs[4], vd[4];
        #pragma unroll
        for (int k = 0; k < 4; k++) vs[k] = __ldg(srow + (t + 8 * k));
        #pragma unroll
        for (int k = 0; k < 4; k++) vd[k] = __ldg(drow + (t + 8 * k));

        float part = 0.f;
        #pragma unroll
        for (int k = 0; k < 4; k++)
            part += vs[k].x * w3v[k].x * vd[k].x + vs[k].y * w3v[k].y * vd[k].y
                  + vs[k].z * w3v[k].z * vd[k].z + vs[k].w * w3v[k].w * vd[k].w;
        part += __shfl_xor_sync(0xffffffffu, part, 4);
        part += __shfl_xor_sync(0xffffffffu, part, 2);
        part += __shfl_xor_sync(0xffffffffu, part, 1);

        if (valid) {
            float* op = out + dst * C;
            #pragma unroll
            for (int k = 0; k < 4; k++) {
                float4 r;
                r.x = part * vs[k].x * w2v[k].x; r.y = part * vs[k].y * w2v[k].y;
                r.z = part * vs[k].z * w2v[k].z; r.w = part * vs[k].w * w2v[k].w;
                asm volatile("red.global.add.v4.f32 [%0], {%1,%2,%3,%4};"
                             :: "l"(op + (t + 8 * k) * 4),
                                "f"(r.x), "f"(r.y), "f"(r.z), "f"(r.w) : "memory");
            }
        }
    }
}

extern "C" void kernel_launch(void* const* d_in, const int* in_sizes, int n_in,
                              void* d_out, int out_size) {
    const float* x  = (const float*)d_in[0];
    const void*  ei = d_in[1];
    const float* W2 = (const float*)d_in[2];
    const float* W3 = (const float*)d_in[3];
    float* out = (float*)d_out;

    int n_nodes = in_sizes[0] / C;
    int n_edges = in_sizes[1] / 2;

    if (n_nodes <= N_MAX && n_edges <= E_MAX) {
        void* cnt_ptr = nullptr;
        void* ovf_ptr = nullptr;
        cudaGetSymbolAddress(&cnt_ptr, g_cnt);
        cudaGetSymbolAddress(&ovf_ptr, g_ovf_cnt);
        cudaMemsetAsync(cnt_ptr, 0, (size_t)n_nodes * sizeof(int), 0);
        cudaMemsetAsync(ovf_ptr, 0, sizeof(int), 0);

        int n_f4 = n_nodes * (C / 4);
        prep_kernel<<<768, 256>>>(x, ei, n_edges, n_nodes, n_f4);

        int warps_per_block = 256 / 32;
        int blocks = (n_nodes + warps_per_block - 1) / warps_per_block;
        gather_kernel<<<blocks, 256>>>(x, W2, W3, out, n_nodes);
    } else {
        detect_idx_kernel<<<1, 32>>>(ei, n_nodes);
        cudaMemsetAsync(out, 0, (size_t)out_size * sizeof(float), 0);
        edge_scatter_kernel<<<2048, 256>>>(x, ei, W2, W3, out, n_edges);
    }
}